// round 16
// baseline (speedup 1.0000x reference)
#include <cuda_runtime.h>
#include <cstdint>
#include <cstddef>

#define BB 4
#define NN 8192
#define SS 2048
#define KK 32
#define DD 64
#define NFPS   8              // FPS CTAs per batch
#define NCONS  116            // consumer CTAs (148 - 32)
#define NCHUNK 1024           // 8192 groups / 8 per chunk

// cross-CTA progress: fps CTA (b,0) publishes #centroids written for batch b
__device__ volatile int g_progress[BB];
// FPS argmax exchange: [batch][parity][sub-cta], key = dist|inv_idx|tag
__device__ volatile unsigned long long g_slot[BB][2][NFPS];

// ---------------- packed f32x2 helpers (per-lane IEEE == scalar) ----------
__device__ __forceinline__ unsigned long long pk2(float lo, float hi) {
    unsigned long long r;
    asm("mov.b64 %0, {%1, %2};" : "=l"(r) : "f"(lo), "f"(hi));
    return r;
}
__device__ __forceinline__ void upk2(unsigned long long v, float& lo, float& hi) {
    asm("mov.b64 {%0, %1}, %2;" : "=f"(lo), "=f"(hi) : "l"(v));
}
__device__ __forceinline__ unsigned long long add2(unsigned long long a, unsigned long long b) {
    unsigned long long r;
    asm("add.rn.f32x2 %0, %1, %2;" : "=l"(r) : "l"(a), "l"(b));
    return r;
}
__device__ __forceinline__ unsigned long long mul2(unsigned long long a, unsigned long long b) {
    unsigned long long r;
    asm("mul.rn.f32x2 %0, %1, %2;" : "=l"(r) : "l"(a), "l"(b));
    return r;
}

// TF32 rounding (round-to-nearest-away, as cuBLAS uses for tf32 operands).
__device__ __forceinline__ float tf32r(float x)
{
    float r;
    asm("cvt.rna.tf32.f32 %0, %1;" : "=f"(r) : "f"(x));
    return r;
}

// m16n8k8 tf32 MMA, D = A*B + D (f32 accumulate).
__device__ __forceinline__ void mma_tf32(float& d0, float& d1, float& d2, float& d3,
                                         uint32_t a0, uint32_t a1, uint32_t a2, uint32_t a3,
                                         uint32_t b0, uint32_t b1)
{
    asm("mma.sync.aligned.m16n8k8.row.col.f32.tf32.tf32.f32 "
        "{%0,%1,%2,%3},{%4,%5,%6,%7},{%8,%9},{%0,%1,%2,%3};"
        : "+f"(d0), "+f"(d1), "+f"(d2), "+f"(d3)
        : "r"(a0), "r"(a1), "r"(a2), "r"(a3), "r"(b0), "r"(b1));
}

__device__ __forceinline__ unsigned long long u64max(unsigned long long a,
                                                     unsigned long long b) {
    return (b > a) ? b : a;
}

__global__ void init_kernel()
{
    int t = threadIdx.x;
    if (t < BB) g_progress[t] = 0;
    if (t < BB * 2 * NFPS)
        ((volatile unsigned long long*)g_slot)[t] = 0ull;
}

// ------------------------------------------------------------------
// ONE persistent kernel, grid = 32 + 116 = 148 CTAs, 256 thr, 131KB smem
// (1 CTA/SM -> all resident -> polling is deadlock-free).
// CTA 0-31:   FPS, 8 CTAs per batch; per-iter cross-CTA argmax via
//             tagged parity slots in L2. Bit-exact math preserved.
// CTA 32-147: consumer: wait progress, warp-per-group ball query,
//             fused tf32-mma 3-layer MLP + k-max (8 groups/chunk).
// ------------------------------------------------------------------
__global__ __launch_bounds__(256, 1)
void fused_kernel(const float* __restrict__ xyz,
                  const float* __restrict__ features,
                  const float* __restrict__ W1, const float* __restrict__ b1,
                  const float* __restrict__ W2, const float* __restrict__ b2,
                  const float* __restrict__ W3, const float* __restrict__ b3,
                  float* __restrict__ newxyz,
                  float* __restrict__ feats_out)
{
    extern __shared__ float smem[];
    __shared__ unsigned long long skey[8];
    __shared__ int scur;

    const int tid  = threadIdx.x;
    const int lane = tid & 31;
    const int wid  = tid >> 5;

    if (blockIdx.x < BB * NFPS) {
        // ================= FPS: 8 CTAs per batch =================
        const int fb = blockIdx.x >> 3;        // batch
        const int fr = blockIdx.x & 7;         // sub-cta (slice owner)
        float4* sxyz = (float4*)smem;          // full 8192-pt copy, 128KB
        const float* xb = xyz + (size_t)fb * NN * 3;

        for (int p = tid; p < NN; p += 256)
            sxyz[p] = make_float4(xb[p * 3], xb[p * 3 + 1], xb[p * 3 + 2], 0.0f);

        // own slice: 1024 points, 4 per thread (2 packed pairs)
        const int gbase = fr * 1024 + tid * 4;
        unsigned long long pxp[2], pyp[2], pzp[2];
        float dist[4];
        {
            const float* sb = xb + (size_t)gbase * 3;
#pragma unroll
            for (int j = 0; j < 2; j++) {
                float x0 = sb[6 * j + 0], y0 = sb[6 * j + 1], z0 = sb[6 * j + 2];
                float x1 = sb[6 * j + 3], y1 = sb[6 * j + 4], z1 = sb[6 * j + 5];
                pxp[j] = pk2(x0, x1); pyp[j] = pk2(y0, y1); pzp[j] = pk2(z0, z1);
                dist[2 * j] = 1e10f; dist[2 * j + 1] = 1e10f;
            }
        }
        __syncthreads();

        int cur = 0;
        for (int s = 0; s < SS; s++) {
            float4 c4 = sxyz[cur];
            if (fr == 0 && tid == 0) {
                float* o = newxyz + ((size_t)fb * SS + s) * 3;
                o[0] = c4.x; o[1] = c4.y; o[2] = c4.z;
                if ((s & 7) == 7) {            // publish every 8 centroids
                    __threadfence();
                    g_progress[fb] = s + 1;
                }
            }
            const unsigned tag = (unsigned)((s + 1) & 0xFFF);
            unsigned long long cx2 = pk2(-c4.x, -c4.x);
            unsigned long long cy2 = pk2(-c4.y, -c4.y);
            unsigned long long cz2 = pk2(-c4.z, -c4.z);
            float bv = -1.0f;
            int   bi = 0;
#pragma unroll
            for (int j = 0; j < 2; j++) {
                unsigned long long dx = add2(pxp[j], cx2);
                unsigned long long dy = add2(pyp[j], cy2);
                unsigned long long dz = add2(pzp[j], cz2);
                unsigned long long dd = add2(add2(mul2(dx, dx), mul2(dy, dy)),
                                             mul2(dz, dz));
                float dl, dh; upk2(dd, dl, dh);
                float n0 = fminf(dist[2 * j],     dl);
                float n1 = fminf(dist[2 * j + 1], dh);
                dist[2 * j]     = n0;
                dist[2 * j + 1] = n1;
                if (n0 > bv) { bv = n0; bi = 2 * j; }      // ascending j +
                if (n1 > bv) { bv = n1; bi = 2 * j + 1; }  // strict > = first
            }
            // thread key: dist(32) | inv_idx(13) | tag(12)
            unsigned db = __float_as_uint(bv); // dist>=0: uint==float order
            unsigned long long tkey =
                ((unsigned long long)db << 32) |
                ((unsigned long long)((8191 - (gbase + bi)) & 0x1FFF) << 12) |
                tag;
            unsigned wm = __reduce_max_sync(0xffffffffu, db);
            unsigned bl = __ballot_sync(0xffffffffu, db == wm);
            int src = __ffs(bl) - 1;           // smallest lane == smallest idx
            unsigned long long wkey = __shfl_sync(0xffffffffu, tkey, src);
            if (lane == 0) skey[wid] = wkey;
            __syncthreads();
            if (wid == 0) {
                // intra-CTA max over 8 warp keys (lanes 0-7)
                unsigned long long k = (lane < 8) ? skey[lane] : 0ull;
#pragma unroll
                for (int off = 1; off <= 4; off <<= 1)
                    k = u64max(k, __shfl_xor_sync(0xffffffffu, k, off));
                if (lane == 0) g_slot[fb][s & 1][fr] = k;   // publish

                // poll all 8 sub-CTA slots for this iteration's tag
                unsigned long long v = 0ull;
                bool ready = (lane >= NFPS);
                do {
                    if (!ready) {
                        v = g_slot[fb][s & 1][lane];
                        ready = ((unsigned)v & 0xFFFu) == tag;
                    }
                } while (!__all_sync(0xffffffffu, ready));
                if (lane >= NFPS) v = 0ull;
#pragma unroll
                for (int off = 1; off <= 4; off <<= 1)
                    v = u64max(v, __shfl_xor_sync(0xffffffffu, v, off));
                if (lane == 0)
                    scur = 8191 - (int)((v >> 12) & 0x1FFF);
            }
            __syncthreads();
            cur = scur;
        }
        return;
    }

    // ===================== consumer: ballq + fused MLP =====================
    const int cc  = blockIdx.x - BB * NFPS;    // 0..115
    const int tig = lane & 3;
    const int gid = lane >> 2;

    float* h0s  = smem;                        // 72*33 = 2376 floats
    float* h1s  = smem + 2376;                 // 64*33 = 2112
    float* h2s  = smem + 4488;                 // 128*33 = 4224
    int*   sgi  = (int*)(smem + 8712);         // 8*32 neighbor idx
    float* sctr = smem + 8968;                 // 8*3 centroids

    for (int t = tid; t < 5 * 33; t += 256) h0s[67 * 33 + t] = 0.0f;

    // ---- W1 fragments: warps 0-3 own 16 channels; K 67 -> 72 zero pad ----
    uint32_t a1f[9][4];
    float bz1_0 = 0.0f, bz1_1 = 0.0f;
    if (wid < 4) {
        int mb = wid * 16;
#pragma unroll
        for (int ks = 0; ks < 9; ks++) {
            int k0 = ks * 8 + tig, k1 = k0 + 4;
            const float* r0 = W1 + (size_t)(mb + gid) * 67;
            const float* r1 = W1 + (size_t)(mb + 8 + gid) * 67;
            a1f[ks][0] = (k0 < 67) ? __float_as_uint(tf32r(r0[k0])) : 0u;
            a1f[ks][1] = (k0 < 67) ? __float_as_uint(tf32r(r1[k0])) : 0u;
            a1f[ks][2] = (k1 < 67) ? __float_as_uint(tf32r(r0[k1])) : 0u;
            a1f[ks][3] = (k1 < 67) ? __float_as_uint(tf32r(r1[k1])) : 0u;
        }
        bz1_0 = b1[mb + gid];
        bz1_1 = b1[mb + 8 + gid];
    }
    // ---- W2 fragments: all 8 warps own 16 channels; K=64 ----
    uint32_t a2f[8][4];
    {
        int mb = wid * 16;
#pragma unroll
        for (int ks = 0; ks < 8; ks++) {
            const float* r0 = W2 + (size_t)(mb + gid) * 64 + ks * 8 + tig;
            const float* r1 = W2 + (size_t)(mb + 8 + gid) * 64 + ks * 8 + tig;
            a2f[ks][0] = __float_as_uint(tf32r(r0[0]));
            a2f[ks][1] = __float_as_uint(tf32r(r1[0]));
            a2f[ks][2] = __float_as_uint(tf32r(r0[4]));
            a2f[ks][3] = __float_as_uint(tf32r(r1[4]));
        }
    }
    const float bz2_0 = b2[wid * 16 + gid];
    const float bz2_1 = b2[wid * 16 + 8 + gid];
    // ---- W3 fragments: all warps own 32 channels (2 m-tiles); K=128 ----
    uint32_t a3f[2][16][4];
    {
        int mb = wid * 32;
#pragma unroll
        for (int mt = 0; mt < 2; mt++)
#pragma unroll
            for (int ks = 0; ks < 16; ks++) {
                const float* wb = W3 + (size_t)(mb + mt * 16 + gid) * 128 + ks * 8 + tig;
                a3f[mt][ks][0] = __float_as_uint(tf32r(wb[0]));
                a3f[mt][ks][1] = __float_as_uint(tf32r(wb[8 * 128]));
                a3f[mt][ks][2] = __float_as_uint(tf32r(wb[4]));
                a3f[mt][ks][3] = __float_as_uint(tf32r(wb[8 * 128 + 4]));
            }
    }
    float bz3[2][2];
#pragma unroll
    for (int mt = 0; mt < 2; mt++) {
        bz3[mt][0] = b3[wid * 32 + mt * 16 + gid];
        bz3[mt][1] = b3[wid * 32 + mt * 16 + 8 + gid];
    }

    // chunk m covers ord = 8m..8m+7, ord = s*4 + b  ->  s <= 2m+1
    for (int m = cc; m < NCHUNK; m += NCONS) {
        const int need = 2 * m + 2;
        if (tid < BB) {
            while (g_progress[tid] < need) __nanosleep(128);
        }
        __syncthreads();
        __threadfence();                       // order data reads after poll

        // ---- ball query: warp w -> ord = 8m + w ----
        {
            int ordg = 8 * m + wid;
            int bq = ordg & 3, sq = ordg >> 2;
            int g  = bq * 2048 + sq;
            const float* xb = xyz + (size_t)bq * NN * 3;
            float nx = __ldcg(newxyz + (size_t)g * 3 + 0);
            float ny = __ldcg(newxyz + (size_t)g * 3 + 1);
            float nz = __ldcg(newxyz + (size_t)g * 3 + 2);
            if (lane == 0) {
                sctr[wid * 3 + 0] = nx; sctr[wid * 3 + 1] = ny;
                sctr[wid * 3 + 2] = nz;
            }
            float nsq = __fadd_rn(__fadd_rn(__fmul_rn(nx, nx), __fmul_rn(ny, ny)),
                                  __fmul_rn(nz, nz));
            int cnt = 0, first = 0;
            int* gdst = sgi + wid * 32;
            for (int base = 0; base < NN; base += 32) {
                int p = base + lane;
                float x = xb[p * 3 + 0];
                float y = xb[p * 3 + 1];
                float z = xb[p * 3 + 2];
                float xsq = __fadd_rn(__fadd_rn(__fmul_rn(x, x), __fmul_rn(y, y)),
                                      __fmul_rn(z, z));
                float dot = __fmaf_rn(nz, z, __fmaf_rn(ny, y, __fmul_rn(nx, x)));
                float sq  = __fsub_rn(__fadd_rn(nsq, xsq), __fmul_rn(2.0f, dot));
                bool hit  = !(sq > 0.04f);
                unsigned hm = __ballot_sync(0xffffffffu, hit);
                if (cnt == 0 && hm) first = base + __ffs(hm) - 1;
                int pos = cnt + __popc(hm & ((1u << lane) - 1u));
                if (hit && pos < KK) gdst[pos] = p;
                cnt += __popc(hm);
                if (cnt >= KK) break;
            }
            if (cnt < KK) {
                for (int k = cnt + lane; k < KK; k += 32) gdst[k] = first;
            }
        }
        __syncthreads();

        // ---- fused MLP for the 8 groups of this chunk ----
        for (int gg = 0; gg < 8; gg++) {
            int ordg = 8 * m + gg;
            int bg = ordg & 3, sg = ordg >> 2;
            int g  = bg * 2048 + sg;

            if (tid < 96) {
                int c = tid >> 5, k = tid & 31;
                float v = xyz[((size_t)bg * NN + sgi[gg * 32 + k]) * 3 + c]
                          - sctr[gg * 3 + c];
                h0s[c * 33 + k] = tf32r(v);
            }
            for (int t = tid; t < 512; t += 256) {
                int k = t >> 4, q = t & 15;
                const float4 v = *(const float4*)(features +
                        ((size_t)bg * NN + sgi[gg * 32 + k]) * DD + q * 4);
                float* dst = &h0s[(3 + 4 * q) * 33 + k];
                dst[0]  = tf32r(v.x);
                dst[33] = tf32r(v.y);
                dst[66] = tf32r(v.z);
                dst[99] = tf32r(v.w);
            }
            __syncthreads();

            if (wid < 4) {
                float d[4][4];
#pragma unroll
                for (int nt = 0; nt < 4; nt++) {
                    d[nt][0] = bz1_0; d[nt][1] = bz1_0;
                    d[nt][2] = bz1_1; d[nt][3] = bz1_1;
                }
#pragma unroll
                for (int ks = 0; ks < 9; ks++)
#pragma unroll
                    for (int nt = 0; nt < 4; nt++) {
                        uint32_t b0 = __float_as_uint(h0s[(ks * 8 + tig) * 33 + nt * 8 + gid]);
                        uint32_t b1v = __float_as_uint(h0s[(ks * 8 + tig + 4) * 33 + nt * 8 + gid]);
                        mma_tf32(d[nt][0], d[nt][1], d[nt][2], d[nt][3],
                                 a1f[ks][0], a1f[ks][1], a1f[ks][2], a1f[ks][3], b0, b1v);
                    }
                int mb = wid * 16;
#pragma unroll
                for (int nt = 0; nt < 4; nt++) {
                    h1s[(mb + gid) * 33 + nt * 8 + 2 * tig]         = tf32r(fmaxf(d[nt][0], 0.0f));
                    h1s[(mb + gid) * 33 + nt * 8 + 2 * tig + 1]     = tf32r(fmaxf(d[nt][1], 0.0f));
                    h1s[(mb + 8 + gid) * 33 + nt * 8 + 2 * tig]     = tf32r(fmaxf(d[nt][2], 0.0f));
                    h1s[(mb + 8 + gid) * 33 + nt * 8 + 2 * tig + 1] = tf32r(fmaxf(d[nt][3], 0.0f));
                }
            }
            __syncthreads();

            {
                float d[4][4];
#pragma unroll
                for (int nt = 0; nt < 4; nt++) {
                    d[nt][0] = bz2_0; d[nt][1] = bz2_0;
                    d[nt][2] = bz2_1; d[nt][3] = bz2_1;
                }
#pragma unroll
                for (int ks = 0; ks < 8; ks++)
#pragma unroll
                    for (int nt = 0; nt < 4; nt++) {
                        uint32_t b0 = __float_as_uint(h1s[(ks * 8 + tig) * 33 + nt * 8 + gid]);
                        uint32_t b1v = __float_as_uint(h1s[(ks * 8 + tig + 4) * 33 + nt * 8 + gid]);
                        mma_tf32(d[nt][0], d[nt][1], d[nt][2], d[nt][3],
                                 a2f[ks][0], a2f[ks][1], a2f[ks][2], a2f[ks][3], b0, b1v);
                    }
                int mb = wid * 16;
#pragma unroll
                for (int nt = 0; nt < 4; nt++) {
                    h2s[(mb + gid) * 33 + nt * 8 + 2 * tig]         = tf32r(fmaxf(d[nt][0], 0.0f));
                    h2s[(mb + gid) * 33 + nt * 8 + 2 * tig + 1]     = tf32r(fmaxf(d[nt][1], 0.0f));
                    h2s[(mb + 8 + gid) * 33 + nt * 8 + 2 * tig]     = tf32r(fmaxf(d[nt][2], 0.0f));
                    h2s[(mb + 8 + gid) * 33 + nt * 8 + 2 * tig + 1] = tf32r(fmaxf(d[nt][3], 0.0f));
                }
            }
            __syncthreads();

            {
                float d[2][4][4];
#pragma unroll
                for (int mt = 0; mt < 2; mt++)
#pragma unroll
                    for (int nt = 0; nt < 4; nt++) {
                        d[mt][nt][0] = bz3[mt][0]; d[mt][nt][1] = bz3[mt][0];
                        d[mt][nt][2] = bz3[mt][1]; d[mt][nt][3] = bz3[mt][1];
                    }
#pragma unroll
                for (int ks = 0; ks < 16; ks++)
#pragma unroll
                    for (int nt = 0; nt < 4; nt++) {
                        uint32_t b0 = __float_as_uint(h2s[(ks * 8 + tig) * 33 + nt * 8 + gid]);
                        uint32_t b1v = __float_as_uint(h2s[(ks * 8 + tig + 4) * 33 + nt * 8 + gid]);
#pragma unroll
                        for (int mt = 0; mt < 2; mt++)
                            mma_tf32(d[mt][nt][0], d[mt][nt][1], d[mt][nt][2], d[mt][nt][3],
                                     a3f[mt][ks][0], a3f[mt][ks][1], a3f[mt][ks][2], a3f[mt][ks][3],
                                     b0, b1v);
                    }
                int mb = wid * 32;
#pragma unroll
                for (int mt = 0; mt < 2; mt++) {
                    float v0 = 0.0f, v1 = 0.0f;    // relu floor
#pragma unroll
                    for (int nt = 0; nt < 4; nt++) {
                        v0 = fmaxf(v0, fmaxf(d[mt][nt][0], d[mt][nt][1]));
                        v1 = fmaxf(v1, fmaxf(d[mt][nt][2], d[mt][nt][3]));
                    }
#pragma unroll
                    for (int off = 1; off <= 2; off <<= 1) {
                        v0 = fmaxf(v0, __shfl_xor_sync(0xffffffffu, v0, off));
                        v1 = fmaxf(v1, __shfl_xor_sync(0xffffffffu, v1, off));
                    }
                    if (tig == 0) {
                        feats_out[(size_t)g * 256 + mb + mt * 16 + gid]     = v0;
                        feats_out[(size_t)g * 256 + mb + mt * 16 + 8 + gid] = v1;
                    }
                }
            }
        }
    }
}

// ------------------------------------------------------------------
extern "C" void kernel_launch(void* const* d_in, const int* in_sizes, int n_in,
                              void* d_out, int out_size)
{
    const float* xyz      = (const float*)d_in[0];
    const float* features = (const float*)d_in[1];
    const float* W1 = (const float*)d_in[2];
    const float* b1 = (const float*)d_in[3];
    const float* W2 = (const float*)d_in[4];
    const float* b2 = (const float*)d_in[5];
    const float* W3 = (const float*)d_in[6];
    const float* b3 = (const float*)d_in[7];

    float* out    = (float*)d_out;
    float* newxyz = out;                         // [B,S,3] = 24576 floats
    float* feats  = out + (size_t)BB * SS * 3;   // [B,S,256]

    const int smem_bytes = NN * (int)sizeof(float4);   // 131072
    cudaFuncSetAttribute(fused_kernel, cudaFuncAttributeMaxDynamicSharedMemorySize,
                         smem_bytes);

    init_kernel<<<1, 128>>>();
    fused_kernel<<<BB * NFPS + NCONS, 256, smem_bytes>>>(
        xyz, features, W1, b1, W2, b2, W3, b3, newxyz, feats);
}

// round 17
// speedup vs baseline: 1.3388x; 1.3388x over previous
#include <cuda_runtime.h>
#include <cstdint>
#include <cstddef>

#define BB 4
#define NN 8192
#define SS 2048
#define KK 32
#define DD 64
#define NCONS  144            // consumer CTAs
#define NCHUNK 1024           // 8192 groups / 8 per chunk

// cross-CTA progress: fps CTA b publishes #centroids written for batch b
__device__ volatile int g_progress[BB];

// ---------------- packed f32x2 helpers (per-lane IEEE == scalar) ----------
__device__ __forceinline__ unsigned long long pk2(float lo, float hi) {
    unsigned long long r;
    asm("mov.b64 %0, {%1, %2};" : "=l"(r) : "f"(lo), "f"(hi));
    return r;
}
__device__ __forceinline__ void upk2(unsigned long long v, float& lo, float& hi) {
    asm("mov.b64 {%0, %1}, %2;" : "=f"(lo), "=f"(hi) : "l"(v));
}
__device__ __forceinline__ unsigned long long add2(unsigned long long a, unsigned long long b) {
    unsigned long long r;
    asm("add.rn.f32x2 %0, %1, %2;" : "=l"(r) : "l"(a), "l"(b));
    return r;
}
__device__ __forceinline__ unsigned long long mul2(unsigned long long a, unsigned long long b) {
    unsigned long long r;
    asm("mul.rn.f32x2 %0, %1, %2;" : "=l"(r) : "l"(a), "l"(b));
    return r;
}

// TF32 rounding (round-to-nearest-away, as cuBLAS uses for tf32 operands).
__device__ __forceinline__ float tf32r(float x)
{
    float r;
    asm("cvt.rna.tf32.f32 %0, %1;" : "=f"(r) : "f"(x));
    return r;
}

// m16n8k8 tf32 MMA, D = A*B + D (f32 accumulate).
__device__ __forceinline__ void mma_tf32(float& d0, float& d1, float& d2, float& d3,
                                         uint32_t a0, uint32_t a1, uint32_t a2, uint32_t a3,
                                         uint32_t b0, uint32_t b1)
{
    asm("mma.sync.aligned.m16n8k8.row.col.f32.tf32.tf32.f32 "
        "{%0,%1,%2,%3},{%4,%5,%6,%7},{%8,%9},{%0,%1,%2,%3};"
        : "+f"(d0), "+f"(d1), "+f"(d2), "+f"(d3)
        : "r"(a0), "r"(a1), "r"(a2), "r"(a3), "r"(b0), "r"(b1));
}

__device__ __forceinline__ unsigned long long u64max(unsigned long long a,
                                                     unsigned long long b) {
    return (b > a) ? b : a;
}

__global__ void init_kernel()
{
    if (threadIdx.x < BB) g_progress[threadIdx.x] = 0;
}

// ------------------------------------------------------------------
// ONE persistent kernel, grid = 4 + 144 = 148 CTAs, 256 thr, 131KB smem
// (1 CTA/SM -> all resident -> polling is deadlock-free).
// CTA 0-3:   FPS for batch b. Single barrier per iteration: warp keys
//            (dist|~idx u64) in parity-double-buffered smem; ALL warps
//            redundantly reduce -> cur. Bit-exact math preserved.
// CTA 4-147: consumer: wait progress, warp-per-group ball query,
//            fused tf32-mma 3-layer MLP + k-max (8 groups/chunk).
// ------------------------------------------------------------------
__global__ __launch_bounds__(256, 1)
void fused_kernel(const float* __restrict__ xyz,
                  const float* __restrict__ features,
                  const float* __restrict__ W1, const float* __restrict__ b1,
                  const float* __restrict__ W2, const float* __restrict__ b2,
                  const float* __restrict__ W3, const float* __restrict__ b3,
                  float* __restrict__ newxyz,
                  float* __restrict__ feats_out)
{
    extern __shared__ float smem[];
    __shared__ unsigned long long skey[2][8];

    const int tid  = threadIdx.x;
    const int lane = tid & 31;
    const int wid  = tid >> 5;

    if (blockIdx.x < BB) {
        // ================= FPS (bit-exact, verified math) =================
        const int b = blockIdx.x;
        float4* sxyz = (float4*)smem;          // 8192 * 16B = 128KB
        const float* xb = xyz + (size_t)b * NN * 3;

        unsigned long long pxp[16], pyp[16], pzp[16];
        float dist[32];
#pragma unroll
        for (int j = 0; j < 16; j++) {
            int p0 = tid * 32 + 2 * j;
            float x0 = xb[p0 * 3 + 0], y0 = xb[p0 * 3 + 1], z0 = xb[p0 * 3 + 2];
            float x1 = xb[p0 * 3 + 3], y1 = xb[p0 * 3 + 4], z1 = xb[p0 * 3 + 5];
            pxp[j] = pk2(x0, x1); pyp[j] = pk2(y0, y1); pzp[j] = pk2(z0, z1);
            dist[2 * j] = 1e10f; dist[2 * j + 1] = 1e10f;
            sxyz[p0]     = make_float4(x0, y0, z0, 0.0f);
            sxyz[p0 + 1] = make_float4(x1, y1, z1, 0.0f);
        }
        __syncthreads();

        int cur = 0;
        for (int s = 0; s < SS; s++) {
            float4 c4 = sxyz[cur];
            if (tid == 0) {
                float* o = newxyz + ((size_t)b * SS + s) * 3;
                o[0] = c4.x; o[1] = c4.y; o[2] = c4.z;
                if ((s & 7) == 7) {            // publish every 8 centroids
                    __threadfence();
                    g_progress[b] = s + 1;
                }
            }
            unsigned long long cx2 = pk2(-c4.x, -c4.x);
            unsigned long long cy2 = pk2(-c4.y, -c4.y);
            unsigned long long cz2 = pk2(-c4.z, -c4.z);
            float bv = -1.0f;
            int   bi = 0;
#pragma unroll
            for (int j = 0; j < 16; j++) {
                unsigned long long dx = add2(pxp[j], cx2);
                unsigned long long dy = add2(pyp[j], cy2);
                unsigned long long dz = add2(pzp[j], cz2);
                unsigned long long dd = add2(add2(mul2(dx, dx), mul2(dy, dy)),
                                             mul2(dz, dz));
                float dl, dh; upk2(dd, dl, dh);
                float n0 = fminf(dist[2 * j],     dl);
                float n1 = fminf(dist[2 * j + 1], dh);
                dist[2 * j]     = n0;
                dist[2 * j + 1] = n1;
                if (n0 > bv) { bv = n0; bi = 2 * j; }      // strict >, asc j:
                if (n1 > bv) { bv = n1; bi = 2 * j + 1; }  // first-index max
            }
            // warp argmax (first-index tie-break via smallest lane)
            unsigned db = __float_as_uint(bv); // dist>=0: uint==float order
            unsigned wm = __reduce_max_sync(0xffffffffu, db);
            unsigned bl = __ballot_sync(0xffffffffu, db == wm);
            int src  = __ffs(bl) - 1;
            int widx = __shfl_sync(0xffffffffu, tid * 32 + bi, src);
            // u64 key: dist | ~idx (max -> max dist, min idx on ties)
            unsigned long long wkey =
                ((unsigned long long)wm << 32) | (unsigned)(~(unsigned)widx);
            const int par = s & 1;
            if (lane == 0) skey[par][wid] = wkey;
            __syncthreads();                   // the ONLY barrier per iter
            // redundant block reduce in every warp (8 keys, lane&7 bcast)
            unsigned long long k = skey[par][lane & 7];
#pragma unroll
            for (int off = 1; off <= 4; off <<= 1)
                k = u64max(k, __shfl_xor_sync(0xffffffffu, k, off));
            cur = (int)(~(unsigned)k);         // low 32 bits -> idx
        }
        return;
    }

    // ===================== consumer: ballq + fused MLP =====================
    const int cc  = blockIdx.x - BB;           // 0..143
    const int tig = lane & 3;
    const int gid = lane >> 2;

    float* h0s  = smem;                        // 72*33 = 2376 floats
    float* h1s  = smem + 2376;                 // 64*33 = 2112
    float* h2s  = smem + 4488;                 // 128*33 = 4224
    int*   sgi  = (int*)(smem + 8712);         // 8*32 neighbor idx
    float* sctr = smem + 8968;                 // 8*3 centroids

    // zero h0s pad rows 67..71 once (never rewritten)
    for (int t = tid; t < 5 * 33; t += 256) h0s[67 * 33 + t] = 0.0f;

    // ---- W1 fragments: warps 0-3 own 16 channels; K 67 -> 72 zero pad ----
    uint32_t a1f[9][4];
    float bz1_0 = 0.0f, bz1_1 = 0.0f;
    if (wid < 4) {
        int mb = wid * 16;
#pragma unroll
        for (int ks = 0; ks < 9; ks++) {
            int k0 = ks * 8 + tig, k1 = k0 + 4;
            const float* r0 = W1 + (size_t)(mb + gid) * 67;
            const float* r1 = W1 + (size_t)(mb + 8 + gid) * 67;
            a1f[ks][0] = (k0 < 67) ? __float_as_uint(tf32r(r0[k0])) : 0u;
            a1f[ks][1] = (k0 < 67) ? __float_as_uint(tf32r(r1[k0])) : 0u;
            a1f[ks][2] = (k1 < 67) ? __float_as_uint(tf32r(r0[k1])) : 0u;
            a1f[ks][3] = (k1 < 67) ? __float_as_uint(tf32r(r1[k1])) : 0u;
        }
        bz1_0 = b1[mb + gid];
        bz1_1 = b1[mb + 8 + gid];
    }
    // ---- W2 fragments: all 8 warps own 16 channels; K=64 ----
    uint32_t a2f[8][4];
    {
        int mb = wid * 16;
#pragma unroll
        for (int ks = 0; ks < 8; ks++) {
            const float* r0 = W2 + (size_t)(mb + gid) * 64 + ks * 8 + tig;
            const float* r1 = W2 + (size_t)(mb + 8 + gid) * 64 + ks * 8 + tig;
            a2f[ks][0] = __float_as_uint(tf32r(r0[0]));
            a2f[ks][1] = __float_as_uint(tf32r(r1[0]));
            a2f[ks][2] = __float_as_uint(tf32r(r0[4]));
            a2f[ks][3] = __float_as_uint(tf32r(r1[4]));
        }
    }
    const float bz2_0 = b2[wid * 16 + gid];
    const float bz2_1 = b2[wid * 16 + 8 + gid];
    // ---- W3 fragments: all warps own 32 channels (2 m-tiles); K=128 ----
    uint32_t a3f[2][16][4];
    {
        int mb = wid * 32;
#pragma unroll
        for (int mt = 0; mt < 2; mt++)
#pragma unroll
            for (int ks = 0; ks < 16; ks++) {
                const float* wb = W3 + (size_t)(mb + mt * 16 + gid) * 128 + ks * 8 + tig;
                a3f[mt][ks][0] = __float_as_uint(tf32r(wb[0]));
                a3f[mt][ks][1] = __float_as_uint(tf32r(wb[8 * 128]));
                a3f[mt][ks][2] = __float_as_uint(tf32r(wb[4]));
                a3f[mt][ks][3] = __float_as_uint(tf32r(wb[8 * 128 + 4]));
            }
    }
    float bz3[2][2];
#pragma unroll
    for (int mt = 0; mt < 2; mt++) {
        bz3[mt][0] = b3[wid * 32 + mt * 16 + gid];
        bz3[mt][1] = b3[wid * 32 + mt * 16 + 8 + gid];
    }

    // chunk m covers ord = 8m..8m+7, ord = s*4 + b  ->  s <= 2m+1
    for (int m = cc; m < NCHUNK; m += NCONS) {
        const int need = 2 * m + 2;
        if (tid < BB) {
            while (g_progress[tid] < need) __nanosleep(128);
        }
        __syncthreads();
        __threadfence();                       // order data reads after poll

        // ---- ball query: warp w -> ord = 8m + w ----
        {
            int ordg = 8 * m + wid;
            int bq = ordg & 3, sq = ordg >> 2;
            int g  = bq * 2048 + sq;
            const float* xb = xyz + (size_t)bq * NN * 3;
            float nx = __ldcg(newxyz + (size_t)g * 3 + 0);
            float ny = __ldcg(newxyz + (size_t)g * 3 + 1);
            float nz = __ldcg(newxyz + (size_t)g * 3 + 2);
            if (lane == 0) {
                sctr[wid * 3 + 0] = nx; sctr[wid * 3 + 1] = ny;
                sctr[wid * 3 + 2] = nz;
            }
            float nsq = __fadd_rn(__fadd_rn(__fmul_rn(nx, nx), __fmul_rn(ny, ny)),
                                  __fmul_rn(nz, nz));
            int cnt = 0, first = 0;
            int* gdst = sgi + wid * 32;
            for (int base = 0; base < NN; base += 32) {
                int p = base + lane;
                float x = xb[p * 3 + 0];
                float y = xb[p * 3 + 1];
                float z = xb[p * 3 + 2];
                float xsq = __fadd_rn(__fadd_rn(__fmul_rn(x, x), __fmul_rn(y, y)),
                                      __fmul_rn(z, z));
                float dot = __fmaf_rn(nz, z, __fmaf_rn(ny, y, __fmul_rn(nx, x)));
                float sq  = __fsub_rn(__fadd_rn(nsq, xsq), __fmul_rn(2.0f, dot));
                bool hit  = !(sq > 0.04f);
                unsigned hm = __ballot_sync(0xffffffffu, hit);
                if (cnt == 0 && hm) first = base + __ffs(hm) - 1;
                int pos = cnt + __popc(hm & ((1u << lane) - 1u));
                if (hit && pos < KK) gdst[pos] = p;
                cnt += __popc(hm);
                if (cnt >= KK) break;
            }
            if (cnt < KK) {
                for (int k = cnt + lane; k < KK; k += 32) gdst[k] = first;
            }
        }
        __syncthreads();

        // ---- fused MLP for the 8 groups of this chunk ----
        for (int gg = 0; gg < 8; gg++) {
            int ordg = 8 * m + gg;
            int bg = ordg & 3, sg = ordg >> 2;
            int g  = bg * 2048 + sg;

            // gather h0 (tf32): rows 0-2 xyz diff, 3-66 features
            if (tid < 96) {
                int c = tid >> 5, k = tid & 31;
                float v = xyz[((size_t)bg * NN + sgi[gg * 32 + k]) * 3 + c]
                          - sctr[gg * 3 + c];
                h0s[c * 33 + k] = tf32r(v);
            }
            for (int t = tid; t < 512; t += 256) {
                int k = t >> 4, q = t & 15;
                const float4 v = *(const float4*)(features +
                        ((size_t)bg * NN + sgi[gg * 32 + k]) * DD + q * 4);
                float* dst = &h0s[(3 + 4 * q) * 33 + k];
                dst[0]  = tf32r(v.x);
                dst[33] = tf32r(v.y);
                dst[66] = tf32r(v.z);
                dst[99] = tf32r(v.w);
            }
            __syncthreads();

            // layer 1: 72 -> 64 (warps 0-3)
            if (wid < 4) {
                float d[4][4];
#pragma unroll
                for (int nt = 0; nt < 4; nt++) {
                    d[nt][0] = bz1_0; d[nt][1] = bz1_0;
                    d[nt][2] = bz1_1; d[nt][3] = bz1_1;
                }
#pragma unroll
                for (int ks = 0; ks < 9; ks++)
#pragma unroll
                    for (int nt = 0; nt < 4; nt++) {
                        uint32_t b0 = __float_as_uint(h0s[(ks * 8 + tig) * 33 + nt * 8 + gid]);
                        uint32_t b1v = __float_as_uint(h0s[(ks * 8 + tig + 4) * 33 + nt * 8 + gid]);
                        mma_tf32(d[nt][0], d[nt][1], d[nt][2], d[nt][3],
                                 a1f[ks][0], a1f[ks][1], a1f[ks][2], a1f[ks][3], b0, b1v);
                    }
                int mb = wid * 16;
#pragma unroll
                for (int nt = 0; nt < 4; nt++) {
                    h1s[(mb + gid) * 33 + nt * 8 + 2 * tig]         = tf32r(fmaxf(d[nt][0], 0.0f));
                    h1s[(mb + gid) * 33 + nt * 8 + 2 * tig + 1]     = tf32r(fmaxf(d[nt][1], 0.0f));
                    h1s[(mb + 8 + gid) * 33 + nt * 8 + 2 * tig]     = tf32r(fmaxf(d[nt][2], 0.0f));
                    h1s[(mb + 8 + gid) * 33 + nt * 8 + 2 * tig + 1] = tf32r(fmaxf(d[nt][3], 0.0f));
                }
            }
            __syncthreads();

            // layer 2: 64 -> 128 (all warps)
            {
                float d[4][4];
#pragma unroll
                for (int nt = 0; nt < 4; nt++) {
                    d[nt][0] = bz2_0; d[nt][1] = bz2_0;
                    d[nt][2] = bz2_1; d[nt][3] = bz2_1;
                }
#pragma unroll
                for (int ks = 0; ks < 8; ks++)
#pragma unroll
                    for (int nt = 0; nt < 4; nt++) {
                        uint32_t b0 = __float_as_uint(h1s[(ks * 8 + tig) * 33 + nt * 8 + gid]);
                        uint32_t b1v = __float_as_uint(h1s[(ks * 8 + tig + 4) * 33 + nt * 8 + gid]);
                        mma_tf32(d[nt][0], d[nt][1], d[nt][2], d[nt][3],
                                 a2f[ks][0], a2f[ks][1], a2f[ks][2], a2f[ks][3], b0, b1v);
                    }
                int mb = wid * 16;
#pragma unroll
                for (int nt = 0; nt < 4; nt++) {
                    h2s[(mb + gid) * 33 + nt * 8 + 2 * tig]         = tf32r(fmaxf(d[nt][0], 0.0f));
                    h2s[(mb + gid) * 33 + nt * 8 + 2 * tig + 1]     = tf32r(fmaxf(d[nt][1], 0.0f));
                    h2s[(mb + 8 + gid) * 33 + nt * 8 + 2 * tig]     = tf32r(fmaxf(d[nt][2], 0.0f));
                    h2s[(mb + 8 + gid) * 33 + nt * 8 + 2 * tig + 1] = tf32r(fmaxf(d[nt][3], 0.0f));
                }
            }
            __syncthreads();

            // layer 3: 128 -> 256 (all warps, 32 ch), relu + k-max epilogue
            {
                float d[2][4][4];
#pragma unroll
                for (int mt = 0; mt < 2; mt++)
#pragma unroll
                    for (int nt = 0; nt < 4; nt++) {
                        d[mt][nt][0] = bz3[mt][0]; d[mt][nt][1] = bz3[mt][0];
                        d[mt][nt][2] = bz3[mt][1]; d[mt][nt][3] = bz3[mt][1];
                    }
#pragma unroll
                for (int ks = 0; ks < 16; ks++)
#pragma unroll
                    for (int nt = 0; nt < 4; nt++) {
                        uint32_t b0 = __float_as_uint(h2s[(ks * 8 + tig) * 33 + nt * 8 + gid]);
                        uint32_t b1v = __float_as_uint(h2s[(ks * 8 + tig + 4) * 33 + nt * 8 + gid]);
#pragma unroll
                        for (int mt = 0; mt < 2; mt++)
                            mma_tf32(d[mt][nt][0], d[mt][nt][1], d[mt][nt][2], d[mt][nt][3],
                                     a3f[mt][ks][0], a3f[mt][ks][1], a3f[mt][ks][2], a3f[mt][ks][3],
                                     b0, b1v);
                    }
                int mb = wid * 32;
#pragma unroll
                for (int mt = 0; mt < 2; mt++) {
                    float v0 = 0.0f, v1 = 0.0f;    // relu floor
#pragma unroll
                    for (int nt = 0; nt < 4; nt++) {
                        v0 = fmaxf(v0, fmaxf(d[mt][nt][0], d[mt][nt][1]));
                        v1 = fmaxf(v1, fmaxf(d[mt][nt][2], d[mt][nt][3]));
                    }
#pragma unroll
                    for (int off = 1; off <= 2; off <<= 1) {
                        v0 = fmaxf(v0, __shfl_xor_sync(0xffffffffu, v0, off));
                        v1 = fmaxf(v1, __shfl_xor_sync(0xffffffffu, v1, off));
                    }
                    if (tig == 0) {
                        feats_out[(size_t)g * 256 + mb + mt * 16 + gid]     = v0;
                        feats_out[(size_t)g * 256 + mb + mt * 16 + 8 + gid] = v1;
                    }
                }
            }
        }
    }
}

// ------------------------------------------------------------------
extern "C" void kernel_launch(void* const* d_in, const int* in_sizes, int n_in,
                              void* d_out, int out_size)
{
    const float* xyz      = (const float*)d_in[0];
    const float* features = (const float*)d_in[1];
    const float* W1 = (const float*)d_in[2];
    const float* b1 = (const float*)d_in[3];
    const float* W2 = (const float*)d_in[4];
    const float* b2 = (const float*)d_in[5];
    const float* W3 = (const float*)d_in[6];
    const float* b3 = (const float*)d_in[7];

    float* out    = (float*)d_out;
    float* newxyz = out;                         // [B,S,3] = 24576 floats
    float* feats  = out + (size_t)BB * SS * 3;   // [B,S,256]

    const int smem_bytes = NN * (int)sizeof(float4);   // 131072
    cudaFuncSetAttribute(fused_kernel, cudaFuncAttributeMaxDynamicSharedMemorySize,
                         smem_bytes);

    init_kernel<<<1, 32>>>();
    fused_kernel<<<BB + NCONS, 256, smem_bytes>>>(
        xyz, features, W1, b1, W2, b2, W3, b3, newxyz, feats);
}